// round 4
// baseline (speedup 1.0000x reference)
#include <cuda_runtime.h>
#include <cuda_bf16.h>
#include <cstdint>

// out[b,c,h,w] = X[b,c,h,w] * mask_tensor[idx[b], c, h, w]
// Mask is constant across (h,w) per (id,c); fixed channels stored as 1.0f,
// so one scalar per (b,c) suffices.
//
// B=4096, C=32, HW=64, CHW=2048. 8,388,608 floats = 2,097,152 float4.
//
// Structure: the flag->idx->mask dependent chain is resolved once per block
// by a 128-thread prologue into smem; the main loop is purely independent
// LDG.128 + LDS + STG.128. Block tile = 8192 floats = 4 batches, grid = 1024
// blocks -> single wave at 8 blocks/SM (no wave-transition tail).

#define NC       32
#define NCHW     2048
#define TPB      256
#define UNROLL   8                             // float4 per thread
#define BATCHES_PER_BLOCK 4                    // TPB*UNROLL*4 / NCHW
#define TOTAL_V  2097152                       // float4 count
#define NBLOCKS  (TOTAL_V / (TPB * UNROLL))    // 1024

// 1 if idx buffer is int64 (LE), 0 if int32.
__device__ int g_idx_is64;

// ids < 60000 < 2^31: int64 LE => every odd 32-bit word is 0; int32 => odd
// words are random ids (P(all 128 zero) ~ 0). Reads stay in first 1 KB.
__global__ void detect_idx_dtype(const int* __restrict__ idx_words) {
    int t = threadIdx.x;
    int nz = 0;
    #pragma unroll
    for (int i = t; i < 128; i += 32)
        nz |= idx_words[2 * i + 1];
    #pragma unroll
    for (int o = 16; o; o >>= 1)
        nz |= __shfl_down_sync(0xFFFFFFFFu, nz, o);
    if (t == 0) g_idx_is64 = (nz == 0) ? 1 : 0;
}

__global__ void __launch_bounds__(TPB, 8)
tied_dropout_kernel(const float4* __restrict__ X,
                    const int*    __restrict__ idx_words,
                    const float*  __restrict__ mask,
                    float4*       __restrict__ out) {
    __shared__ float sm_mask[BATCHES_PER_BLOCK * NC];   // 4 batches x 32 ch = 128

    const int tid = threadIdx.x;

    // ── Prologue: resolve flag -> idx -> mask once per block ──
    if (tid < BATCHES_PER_BLOCK * NC) {
        const int b_local = tid >> 5;            // 0..3
        const int c       = tid & (NC - 1);      // 0..31
        const int b       = BATCHES_PER_BLOCK * blockIdx.x + b_local;
        const int stride  = g_idx_is64 ? 2 : 1;
        const int id      = idx_words[b * stride];
        sm_mask[tid] = __ldg(&mask[id * NCHW + (c << 6)]);
    }
    __syncthreads();

    // ── Main: two pipelined groups of 4 independent LDG.128/STG.128 ──
    const int base = blockIdx.x * (TPB * UNROLL) + tid;

    #pragma unroll
    for (int g = 0; g < 2; g++) {
        float4 x[4];
        #pragma unroll
        for (int i = 0; i < 4; i++)
            x[i] = X[base + (g * 4 + i) * TPB];

        #pragma unroll
        for (int i = 0; i < 4; i++) {
            const int le = ((g * 4 + i) * TPB + tid) << 2;  // float offset in tile
            // b_local = bits 11..12 ; c = bits 6..10  -> combined bits 6..12
            const float m = sm_mask[(le >> 6) & 127];
            x[i].x *= m; x[i].y *= m; x[i].z *= m; x[i].w *= m;
            out[base + (g * 4 + i) * TPB] = x[i];
        }
    }
}

extern "C" void kernel_launch(void* const* d_in, const int* in_sizes, int n_in,
                              void* d_out, int out_size) {
    const float4* X         = (const float4*)d_in[0];
    const int*    idx_words = (const int*)d_in[1];
    const float*  mask      = (const float*)d_in[2];
    float4*       out       = (float4*)d_out;

    detect_idx_dtype<<<1, 32>>>(idx_words);
    tied_dropout_kernel<<<NBLOCKS, TPB>>>(X, idx_words, mask, out);
}

// round 5
// speedup vs baseline: 1.0286x; 1.0286x over previous
#include <cuda_runtime.h>
#include <cuda_bf16.h>
#include <cstdint>

// out[b,c,h,w] = X[b,c,h,w] * mask_tensor[idx[b], c, h, w]
// Mask is constant across (h,w) per (id,c); fixed channels stored as 1.0f,
// so one scalar per (b,c) suffices.
//
// B=4096, C=32, HW=64, CHW=2048. 8,388,608 floats = 2,097,152 float4.
//
// Single-kernel design: idx-dtype (int64 vs int32) detection is done
// per-warp inside the prologue (speculative loads + shuffle OR over odd
// words — all-zero <=> int64 LE, since ids < 60000 < 2^31). No separate
// detect kernel, so the graph has exactly one node.

#define NC       32
#define NCHW     2048
#define TPB      256
#define UNROLL   8                             // float4 per thread
#define BPB      4                             // batches per block
#define TOTAL_V  2097152                       // float4 count
#define NBLOCKS  (TOTAL_V / (TPB * UNROLL))    // 1024

__global__ void __launch_bounds__(TPB)
tied_dropout_kernel(const float4* __restrict__ X,
                    const int*    __restrict__ idx_words,
                    const float*  __restrict__ mask,
                    float4*       __restrict__ out) {
    __shared__ float sm_mask[BPB * NC];        // 4 batches x 32 channels

    const int tid  = threadIdx.x;
    const int base = blockIdx.x * (TPB * UNROLL) + tid;

    // ── Issue group-0 streaming loads first: prologue latency hides here ──
    float4 xa[4];
    #pragma unroll
    for (int i = 0; i < 4; i++)
        xa[i] = X[base + i * TPB];

    // ── Prologue (4 warps): detect dtype + gather 1 mask scalar per (b,c) ──
    if (tid < BPB * NC) {
        const int lane = tid & 31;             // channel c
        const int w    = tid >> 5;             // batch within block
        const int b    = BPB * blockIdx.x + w;

        // Per-warp dtype detection: sample odd 32-bit words 1,3,...,63.
        // int64 LE -> all high words zero. int32 -> random ids, P(all 0)~0.
        // Reads stay within the first 256 B (int32 buffer is 16 KB).
        int odd = idx_words[2 * lane + 1];
        #pragma unroll
        for (int o = 16; o; o >>= 1)
            odd |= __shfl_xor_sync(0xFFFFFFFFu, odd, o);

        // Speculative loads of both interpretations (warp-uniform address).
        const int id32 = idx_words[b];         // int32 layout
        const int id64 = idx_words[2 * b];     // int64 layout (low word)
        const int id   = (odd == 0) ? id64 : id32;

        sm_mask[tid] = __ldg(&mask[id * NCHW + (lane << 6)]);
    }
    __syncthreads();

    // ── Issue group-1 loads, then process both groups ──
    float4 xb[4];
    #pragma unroll
    for (int i = 0; i < 4; i++)
        xb[i] = X[base + (4 + i) * TPB];

    #pragma unroll
    for (int i = 0; i < 4; i++) {
        const int le = (i * TPB + tid) << 2;   // float offset in block tile
        const float m = sm_mask[(le >> 6) & (BPB * NC - 1)];
        xa[i].x *= m; xa[i].y *= m; xa[i].z *= m; xa[i].w *= m;
        out[base + i * TPB] = xa[i];
    }
    #pragma unroll
    for (int i = 0; i < 4; i++) {
        const int le = ((4 + i) * TPB + tid) << 2;
        const float m = sm_mask[(le >> 6) & (BPB * NC - 1)];
        xb[i].x *= m; xb[i].y *= m; xb[i].z *= m; xb[i].w *= m;
        out[base + (4 + i) * TPB] = xb[i];
    }
}

extern "C" void kernel_launch(void* const* d_in, const int* in_sizes, int n_in,
                              void* d_out, int out_size) {
    const float4* X         = (const float4*)d_in[0];
    const int*    idx_words = (const int*)d_in[1];
    const float*  mask      = (const float*)d_in[2];
    float4*       out       = (float4*)d_out;

    tied_dropout_kernel<<<NBLOCKS, TPB>>>(X, idx_words, mask, out);
}